// round 6
// baseline (speedup 1.0000x reference)
#include <cuda_runtime.h>
#include <math_constants.h>

// EMDLoss (Sinkhorn, eps=0.005, 50 iters), B=8, N=2048, dim=3.
// Morton-sorted sets; log2-domain factored cost. j-range split in halves
// (grid 1024, 16KB tables) for occupancy. No potential arrays: per-row,
// per-half state (s, mx, mu); consumers reconstruct lse on the fly using
// t.w = -log2(N) - lse (qq cancels). Fixed carried-max threshold => the
// ex2 path only fires on genuine survivor chunks.

#define BB 8
#define NN 2048
#define HALFN 1024

static __device__ float4 d_P4[BB * NN];   // sorted (x,y,z, |p|^2*S2)
static __device__ float4 d_Q4[BB * NN];
static __device__ float d_sP[2][BB * NN], d_mxP[2][BB * NN], d_muP[2][BB * NN];
static __device__ float d_sQ[2][BB * NN], d_mxQ[2][BB * NN], d_muQ[2][BB * NN];
static __device__ float d_partials[1024];

__device__ __forceinline__ float ex2f_(float x) {
    float r; asm("ex2.approx.f32 %0, %1;" : "=f"(r) : "f"(x)); return r;
}
__device__ __forceinline__ float lg2f_(float x) {
    float r; asm("lg2.approx.f32 %0, %1;" : "=f"(r) : "f"(x)); return r;
}

#define S2F      288.5390081777927f      // 1/(eps*ln2)
#define S2X2     577.0780163555854f      // 2/(eps*ln2)
#define EPSLN2   0.0034657359027997f     // eps*ln2
#define EPSLOGMU (-0.03812309493079699f) // eps * (-ln N)
#define TT       25.0f                   // truncation window (log2)
#define SLACKTT  37.0f                   // SLACK(12) + TT
#define TTL      33.0f                   // loss truncation (log2)
#define LOG2N    11.0f                   // log2(2048)

// lse of a row from its two half-states.
__device__ __forceinline__ float lse_at(int j,
    const float* __restrict__ s0, const float* __restrict__ s1,
    const float* __restrict__ mx0, const float* __restrict__ mx1,
    const float* __restrict__ mu0, const float* __restrict__ mu1) {
    float m = fmaxf(mx0[j], mx1[j]);
    float t = fmaf(s0[j], ex2f_(mu0[j] - m), s1[j] * ex2f_(mu1[j] - m));
    return m + lg2f_(t);
}

// ---------------------------------------------------------------------------
__global__ void __launch_bounds__(256) prep_sort_kernel(
    const float* __restrict__ preds, const float* __restrict__ gts) {
    int blk = blockIdx.x;
    int b = blk >> 1;
    int set = blk & 1;
    const float* src = set ? gts : preds;
    float4* dst = set ? d_Q4 : d_P4;
    int off = b * NN;

    __shared__ unsigned skey[NN];

    for (int i = threadIdx.x; i < NN; i += 256) {
        const float* p = src + (off + i) * 3;
        float x = p[0], y = p[1], z = p[2];
        int ux = (int)floorf((x + 4.f) * 4.f); ux = min(31, max(0, ux));
        int uy = (int)floorf((y + 4.f) * 4.f); uy = min(31, max(0, uy));
        int uz = (int)floorf((z + 4.f) * 4.f); uz = min(31, max(0, uz));
        unsigned key = 0;
#pragma unroll
        for (int bit = 0; bit < 5; ++bit) {
            key |= (((unsigned)ux >> bit) & 1u) << (3 * bit + 2);
            key |= (((unsigned)uy >> bit) & 1u) << (3 * bit + 1);
            key |= (((unsigned)uz >> bit) & 1u) << (3 * bit + 0);
        }
        skey[i] = (key << 11) | (unsigned)i;
    }
    __syncthreads();

    for (int k = 2; k <= NN; k <<= 1) {
        for (int j = k >> 1; j > 0; j >>= 1) {
            for (int i = threadIdx.x; i < NN; i += 256) {
                int l = i ^ j;
                if (l > i) {
                    unsigned a = skey[i], c = skey[l];
                    bool up = ((i & k) == 0);
                    if ((a > c) == up) { skey[i] = c; skey[l] = a; }
                }
            }
            __syncthreads();
        }
    }

    for (int i = threadIdx.x; i < NN; i += 256) {
        int si = (int)(skey[i] & 2047u);
        const float* p = src + (off + si) * 3;
        float x = p[0], y = p[1], z = p[2];
        dst[off + i] = make_float4(x, y, z, (x * x + y * y + z * z) * S2F);
    }
}

// ---------------------------------------------------------------------------
#define MERGEROW(m, s, off)                                         \
    {                                                               \
        float mo = __shfl_xor_sync(0xffffffffu, m, off);            \
        float so = __shfl_xor_sync(0xffffffffu, s, off);            \
        float mn = fmaxf(m, mo);                                    \
        s = fmaf(so, ex2f_(mo - mn), s * ex2f_(m - mn));            \
        m = mn;                                                     \
    }

#define ROWUPD(m, s, mt, a, e)                                      \
    if (__any_sync(0xffffffffu, (e) > 0.f)) {                       \
        if (__any_sync(0xffffffffu, (a) > (m))) {                   \
            float c = fmaxf(m, a);                                  \
            c = fmaxf(c, __shfl_xor_sync(0xffffffffu, c, 16));      \
            c = fmaxf(c, __shfl_xor_sync(0xffffffffu, c, 8));       \
            c = fmaxf(c, __shfl_xor_sync(0xffffffffu, c, 4));       \
            c = fmaxf(c, __shfl_xor_sync(0xffffffffu, c, 2));       \
            c = fmaxf(c, __shfl_xor_sync(0xffffffffu, c, 1));       \
            s = fmaf(s, ex2f_(m - c), ex2f_((a) - c));              \
            m = c; mt = c - TT;                                     \
        } else {                                                    \
            s += ex2f_((a) - m);                                    \
        }                                                           \
    }

// Shared block-index decode: grid = BB * 64chunks * 2 halves.
#define DECODE_BLK()                                                \
    int blk = blockIdx.x;                                           \
    int b = blk >> 7;                                               \
    int rest = blk & 127;                                           \
    int chunk = rest >> 1;                                          \
    int half = rest & 1;                                            \
    int off = b * NN;

// Table load: 1024 j's of opposite side into smem (reconstructed lse).
#define LOAD_TABLE(D4, TS0, TS1, TMX0, TMX1, TMU0, TMU1)            \
    for (int t = threadIdx.x; t < HALFN; t += 256) {                \
        int j = off + (half << 10) + t;                             \
        float4 q = D4[j];                                           \
        float lse = lse_at(j, TS0, TS1, TMX0, TMX1, TMU0, TMU1);    \
        float4 tt;                                                  \
        tt.x = q.x * S2X2;                                          \
        tt.y = q.y * S2X2;                                          \
        tt.z = q.z * S2X2;                                          \
        tt.w = -LOG2N - lse;   /* = pot*S2 - qq */                  \
        tbl[t] = tt;                                                \
    }

#define LOAD_TABLE_INIT(D4)                                         \
    for (int t = threadIdx.x; t < HALFN; t += 256) {                \
        int j = off + (half << 10) + t;                             \
        float4 q = D4[j];                                           \
        float4 tt;                                                  \
        tt.x = q.x * S2X2;                                          \
        tt.y = q.y * S2X2;                                          \
        tt.z = q.z * S2X2;                                          \
        tt.w = -q.w;           /* pot = 0 */                        \
        tbl[t] = tt;                                                \
    }

#define PICK_SIDES()                                                \
    const float4* R4 = dir ? d_Q4 : d_P4;                           \
    const float4* D4 = dir ? d_P4 : d_Q4;                           \
    const float *ts0, *ts1, *tmx0, *tmx1, *tmu0, *tmu1;             \
    float *rs, *rmx, *rmu;                                          \
    const float *rmxA, *rmxB;                                       \
    if (dir) {                                                      \
        ts0 = d_sP[0];  ts1 = d_sP[1];                              \
        tmx0 = d_mxP[0]; tmx1 = d_mxP[1];                           \
        tmu0 = d_muP[0]; tmu1 = d_muP[1];                           \
        rs = d_sQ[half]; rmx = d_mxQ[half]; rmu = d_muQ[half];      \
        rmxA = d_mxQ[0]; rmxB = d_mxQ[1];                           \
    } else {                                                        \
        ts0 = d_sQ[0];  ts1 = d_sQ[1];                              \
        tmx0 = d_mxQ[0]; tmx1 = d_mxQ[1];                           \
        tmu0 = d_muQ[0]; tmu1 = d_muQ[1];                           \
        rs = d_sP[half]; rmx = d_mxP[half]; rmu = d_muP[half];      \
        rmxA = d_mxP[0]; rmxB = d_mxP[1];                           \
    }

// Boot half-update: full online LSE over this j-half; stores (s, mx=m, mu=m).
__global__ void __launch_bounds__(256) half_boot(int dir) {
    DECODE_BLK();
    PICK_SIDES();
    (void)rmxA; (void)rmxB;

    __shared__ float4 tbl[HALFN];
    if (dir == 0) {
        LOAD_TABLE_INIT(D4)
    } else {
        LOAD_TABLE(D4, ts0, ts1, tmx0, tmx1, tmu0, tmu1)
    }
    __syncthreads();

    int warp = threadIdx.x >> 5;
    int lane = threadIdx.x & 31;
    int row0 = off + chunk * 32 + warp * 4;

    float4 r0 = R4[row0 + 0];
    float4 r1 = R4[row0 + 1];
    float4 r2 = R4[row0 + 2];
    float4 r3 = R4[row0 + 3];

    const float NEGINF = -CUDART_INF_F;
    float m0 = NEGINF, m1 = NEGINF, m2 = NEGINF, m3 = NEGINF;
    float s0 = 0.f, s1 = 0.f, s2 = 0.f, s3 = 0.f;
    float mt0 = NEGINF, mt1 = NEGINF, mt2 = NEGINF, mt3 = NEGINF;

#pragma unroll 2
    for (int k = 0; k < 32; ++k) {
        float4 q = tbl[(k << 5) + lane];
        float a0 = fmaf(r0.x, q.x, fmaf(r0.y, q.y, fmaf(r0.z, q.z, q.w)));
        float a1 = fmaf(r1.x, q.x, fmaf(r1.y, q.y, fmaf(r1.z, q.z, q.w)));
        float a2 = fmaf(r2.x, q.x, fmaf(r2.y, q.y, fmaf(r2.z, q.z, q.w)));
        float a3 = fmaf(r3.x, q.x, fmaf(r3.y, q.y, fmaf(r3.z, q.z, q.w)));
        float e0 = a0 - mt0;
        float e1 = a1 - mt1;
        float e2 = a2 - mt2;
        float e3 = a3 - mt3;
        float emax = fmaxf(fmaxf(e0, e1), fmaxf(e2, e3));
        if (__any_sync(0xffffffffu, emax > 0.f)) {
            ROWUPD(m0, s0, mt0, a0, e0)
            ROWUPD(m1, s1, mt1, a1, e1)
            ROWUPD(m2, s2, mt2, a2, e2)
            ROWUPD(m3, s3, mt3, a3, e3)
        }
    }

#pragma unroll
    for (int o = 16; o; o >>= 1) {
        MERGEROW(m0, s0, o);
        MERGEROW(m1, s1, o);
        MERGEROW(m2, s2, o);
        MERGEROW(m3, s3, o);
    }

    if (lane == 0) {
        rs[row0 + 0] = s0; rmx[row0 + 0] = m0; rmu[row0 + 0] = m0;
        rs[row0 + 1] = s1; rmx[row0 + 1] = m1; rmu[row0 + 1] = m1;
        rs[row0 + 2] = s2; rmx[row0 + 2] = m2; rmu[row0 + 2] = m2;
        rs[row0 + 3] = s3; rmx[row0 + 3] = m3; rmu[row0 + 3] = m3;
    }
}

// Fast half-update: fixed threshold per row muT = max(mx halves) - SLACKTT.
__global__ void __launch_bounds__(256) half_fast(int dir) {
    DECODE_BLK();
    PICK_SIDES();

    __shared__ float4 tbl[HALFN];
    LOAD_TABLE(D4, ts0, ts1, tmx0, tmx1, tmu0, tmu1)
    __syncthreads();

    int warp = threadIdx.x >> 5;
    int lane = threadIdx.x & 31;
    int row0 = off + chunk * 32 + warp * 4;

    float4 r0 = R4[row0 + 0];
    float4 r1 = R4[row0 + 1];
    float4 r2 = R4[row0 + 2];
    float4 r3 = R4[row0 + 3];

    float muT0 = fmaxf(rmxA[row0 + 0], rmxB[row0 + 0]) - SLACKTT;
    float muT1 = fmaxf(rmxA[row0 + 1], rmxB[row0 + 1]) - SLACKTT;
    float muT2 = fmaxf(rmxA[row0 + 2], rmxB[row0 + 2]) - SLACKTT;
    float muT3 = fmaxf(rmxA[row0 + 3], rmxB[row0 + 3]) - SLACKTT;
    // common conservative trigger threshold (rows are Morton-adjacent)
    float muTc = fminf(fminf(muT0, muT1), fminf(muT2, muT3));

    const float NEGINF = -CUDART_INF_F;
    float s0 = 0.f, s1 = 0.f, s2 = 0.f, s3 = 0.f;
    float mx0 = NEGINF, mx1 = NEGINF, mx2 = NEGINF, mx3 = NEGINF;

#pragma unroll 2
    for (int k = 0; k < 32; ++k) {
        float4 q = tbl[(k << 5) + lane];
        float a0 = fmaf(r0.x, q.x, fmaf(r0.y, q.y, fmaf(r0.z, q.z, q.w)));
        float a1 = fmaf(r1.x, q.x, fmaf(r1.y, q.y, fmaf(r1.z, q.z, q.w)));
        float a2 = fmaf(r2.x, q.x, fmaf(r2.y, q.y, fmaf(r2.z, q.z, q.w)));
        float a3 = fmaf(r3.x, q.x, fmaf(r3.y, q.y, fmaf(r3.z, q.z, q.w)));
        mx0 = fmaxf(mx0, a0);
        mx1 = fmaxf(mx1, a1);
        mx2 = fmaxf(mx2, a2);
        mx3 = fmaxf(mx3, a3);
        float amax = fmaxf(fmaxf(a0, a1), fmaxf(a2, a3));
        if (__any_sync(0xffffffffu, amax > muTc)) {
            s0 += ex2f_(a0 - muT0);   // negative args underflow harmlessly
            s1 += ex2f_(a1 - muT1);
            s2 += ex2f_(a2 - muT2);
            s3 += ex2f_(a3 - muT3);
        }
    }

#pragma unroll
    for (int o = 16; o; o >>= 1) {
        s0 += __shfl_xor_sync(0xffffffffu, s0, o);
        s1 += __shfl_xor_sync(0xffffffffu, s1, o);
        s2 += __shfl_xor_sync(0xffffffffu, s2, o);
        s3 += __shfl_xor_sync(0xffffffffu, s3, o);
        mx0 = fmaxf(mx0, __shfl_xor_sync(0xffffffffu, mx0, o));
        mx1 = fmaxf(mx1, __shfl_xor_sync(0xffffffffu, mx1, o));
        mx2 = fmaxf(mx2, __shfl_xor_sync(0xffffffffu, mx2, o));
        mx3 = fmaxf(mx3, __shfl_xor_sync(0xffffffffu, mx3, o));
    }

    if (lane == 0) {
        rs[row0 + 0] = s0; rmx[row0 + 0] = mx0; rmu[row0 + 0] = muT0;
        rs[row0 + 1] = s1; rmx[row0 + 1] = mx1; rmu[row0 + 1] = muT1;
        rs[row0 + 2] = s2; rmx[row0 + 2] = mx2; rmu[row0 + 2] = muT2;
        rs[row0 + 3] = s3; rmx[row0 + 3] = mx3; rmu[row0 + 3] = muT3;
    }
}

// ---------------------------------------------------------------------------
// Loss: part += P_ij * C_ij, truncated. Reconstructs f and g from state.
__global__ void __launch_bounds__(256) loss_kernel() {
    DECODE_BLK();

    __shared__ float4 tbl[HALFN];
    __shared__ float  gg[HALFN];
    for (int t = threadIdx.x; t < HALFN; t += 256) {
        int j = off + (half << 10) + t;
        float4 q = d_Q4[j];
        float lse = lse_at(j, d_sQ[0], d_sQ[1], d_mxQ[0], d_mxQ[1],
                           d_muQ[0], d_muQ[1]);
        float gj = fmaf(-EPSLN2, (-q.w) + lse, EPSLOGMU);
        float4 tt;
        tt.x = q.x * S2X2;
        tt.y = q.y * S2X2;
        tt.z = q.z * S2X2;
        tt.w = -LOG2N - lse;
        tbl[t] = tt;
        gg[t] = gj;
    }
    __syncthreads();

    int warp = threadIdx.x >> 5;
    int lane = threadIdx.x & 31;
    int row0 = off + chunk * 32 + warp * 4;

    float4 r0 = d_P4[row0 + 0];
    float4 r1 = d_P4[row0 + 1];
    float4 r2 = d_P4[row0 + 2];
    float4 r3 = d_P4[row0 + 3];

    float lse0 = lse_at(row0 + 0, d_sP[0], d_sP[1], d_mxP[0], d_mxP[1], d_muP[0], d_muP[1]);
    float lse1 = lse_at(row0 + 1, d_sP[0], d_sP[1], d_mxP[0], d_mxP[1], d_muP[0], d_muP[1]);
    float lse2 = lse_at(row0 + 2, d_sP[0], d_sP[1], d_mxP[0], d_mxP[1], d_muP[0], d_muP[1]);
    float lse3 = lse_at(row0 + 3, d_sP[0], d_sP[1], d_mxP[0], d_mxP[1], d_muP[0], d_muP[1]);

    float fr0 = fmaf(-EPSLN2, (-r0.w) + lse0, EPSLOGMU);
    float fr1 = fmaf(-EPSLN2, (-r1.w) + lse1, EPSLOGMU);
    float fr2 = fmaf(-EPSLN2, (-r2.w) + lse2, EPSLOGMU);
    float fr3 = fmaf(-EPSLN2, (-r3.w) + lse3, EPSLOGMU);

    // ffT = f*S2 - pp*S2 + TTL = -LOG2N - lse + TTL
    float ffT0 = -LOG2N - lse0 + TTL;
    float ffT1 = -LOG2N - lse1 + TTL;
    float ffT2 = -LOG2N - lse2 + TTL;
    float ffT3 = -LOG2N - lse3 + TTL;
    // trigger: e_i = a_i + ffT_i > 0 for some i  =>  amax > cthr
    float cthr = -fmaxf(fmaxf(ffT0, ffT1), fmaxf(ffT2, ffT3));

    float part = 0.f;
#pragma unroll 2
    for (int k = 0; k < 32; ++k) {
        int j = (k << 5) + lane;
        float4 q = tbl[j];
        float a0 = fmaf(r0.x, q.x, fmaf(r0.y, q.y, fmaf(r0.z, q.z, q.w)));
        float a1 = fmaf(r1.x, q.x, fmaf(r1.y, q.y, fmaf(r1.z, q.z, q.w)));
        float a2 = fmaf(r2.x, q.x, fmaf(r2.y, q.y, fmaf(r2.z, q.z, q.w)));
        float a3 = fmaf(r3.x, q.x, fmaf(r3.y, q.y, fmaf(r3.z, q.z, q.w)));
        float amax = fmaxf(fmaxf(a0, a1), fmaxf(a2, a3));
        if (__any_sync(0xffffffffu, amax > cthr)) {
            float gj = gg[j];
            {
                float arg = (a0 + ffT0) - TTL;
                float C = fmaf(-EPSLN2, arg, fr0 + gj);
                part = fmaf(ex2f_(arg), C, part);
            }
            {
                float arg = (a1 + ffT1) - TTL;
                float C = fmaf(-EPSLN2, arg, fr1 + gj);
                part = fmaf(ex2f_(arg), C, part);
            }
            {
                float arg = (a2 + ffT2) - TTL;
                float C = fmaf(-EPSLN2, arg, fr2 + gj);
                part = fmaf(ex2f_(arg), C, part);
            }
            {
                float arg = (a3 + ffT3) - TTL;
                float C = fmaf(-EPSLN2, arg, fr3 + gj);
                part = fmaf(ex2f_(arg), C, part);
            }
        }
    }

    __shared__ float red[256];
    red[threadIdx.x] = part;
    __syncthreads();
#pragma unroll
    for (int o = 128; o; o >>= 1) {
        if (threadIdx.x < o) red[threadIdx.x] += red[threadIdx.x + o];
        __syncthreads();
    }
    if (threadIdx.x == 0) d_partials[blockIdx.x] = red[0];
}

__global__ void reduce_kernel(float* __restrict__ out) {
    __shared__ float red[256];
    float v = 0.f;
    for (int i = threadIdx.x; i < 1024; i += 256) v += d_partials[i];
    red[threadIdx.x] = v;
    __syncthreads();
#pragma unroll
    for (int o = 128; o; o >>= 1) {
        if (threadIdx.x < o) red[threadIdx.x] += red[threadIdx.x + o];
        __syncthreads();
    }
    if (threadIdx.x == 0) out[0] = red[0] * 0.125f;
}

extern "C" void kernel_launch(void* const* d_in, const int* in_sizes, int n_in,
                              void* d_out, int out_size) {
    const float* preds = (const float*)d_in[0];
    const float* gts   = (const float*)d_in[1];
    float* out = (float*)d_out;

    prep_sort_kernel<<<BB * 2, 256>>>(preds, gts);
    half_boot<<<BB * 128, 256>>>(0);
    half_boot<<<BB * 128, 256>>>(1);
    for (int it = 1; it < 50; ++it) {
        half_fast<<<BB * 128, 256>>>(0);
        half_fast<<<BB * 128, 256>>>(1);
    }
    loss_kernel<<<BB * 128, 256>>>();
    reduce_kernel<<<1, 256>>>(out);
}

// round 7
// speedup vs baseline: 1.0260x; 1.0260x over previous
#include <cuda_runtime.h>
#include <math_constants.h>

// EMDLoss (Sinkhorn, eps=0.005, 50 iters), B=8, N=2048, dim=3.
// Morton-sorted sets; log2-domain factored cost. Iterations 1..49 use a
// BRANCH-FREE fixed-threshold kernel: s += ex2(a - muT) every element;
// fp32 underflow implements the truncation. muT = prev row max - 37.
// Exact row max carried via FMNMX on the (otherwise idle) ALU pipe.

#define BB 8
#define NN 2048

static __device__ float4 d_P4[BB * NN];   // sorted (x,y,z, |p|^2*S2)
static __device__ float4 d_Q4[BB * NN];
static __device__ float  d_f[BB * NN];
static __device__ float  d_g[BB * NN];
static __device__ float  d_mf[BB * NN];
static __device__ float  d_mg[BB * NN];
static __device__ float  d_partials[512];

__device__ __forceinline__ float ex2f_(float x) {
    float r; asm("ex2.approx.f32 %0, %1;" : "=f"(r) : "f"(x)); return r;
}
__device__ __forceinline__ float lg2f_(float x) {
    float r; asm("lg2.approx.f32 %0, %1;" : "=f"(r) : "f"(x)); return r;
}

#define S2F      288.5390081777927f      // 1/(eps*ln2)
#define S2X2     577.0780163555854f      // 2/(eps*ln2)
#define EPSLN2   0.0034657359027997f     // eps*ln2
#define EPSLOGMU (-0.03812309493079699f) // eps * (-ln N)
#define TT       25.0f                   // truncation window (log2)
#define SLACKTT  37.0f                   // SLACK(12) + TT
#define TTL      33.0f                   // loss truncation (log2)

// ---------------------------------------------------------------------------
__global__ void __launch_bounds__(256) prep_sort_kernel(
    const float* __restrict__ preds, const float* __restrict__ gts) {
    int blk = blockIdx.x;
    int b = blk >> 1;
    int set = blk & 1;
    const float* src = set ? gts : preds;
    float4* dst = set ? d_Q4 : d_P4;
    float*  pot = set ? d_g  : d_f;
    int off = b * NN;

    __shared__ unsigned skey[NN];

    for (int i = threadIdx.x; i < NN; i += 256) {
        const float* p = src + (off + i) * 3;
        float x = p[0], y = p[1], z = p[2];
        int ux = (int)floorf((x + 4.f) * 4.f); ux = min(31, max(0, ux));
        int uy = (int)floorf((y + 4.f) * 4.f); uy = min(31, max(0, uy));
        int uz = (int)floorf((z + 4.f) * 4.f); uz = min(31, max(0, uz));
        unsigned key = 0;
#pragma unroll
        for (int bit = 0; bit < 5; ++bit) {
            key |= (((unsigned)ux >> bit) & 1u) << (3 * bit + 2);
            key |= (((unsigned)uy >> bit) & 1u) << (3 * bit + 1);
            key |= (((unsigned)uz >> bit) & 1u) << (3 * bit + 0);
        }
        skey[i] = (key << 11) | (unsigned)i;
    }
    __syncthreads();

    for (int k = 2; k <= NN; k <<= 1) {
        for (int j = k >> 1; j > 0; j >>= 1) {
            for (int i = threadIdx.x; i < NN; i += 256) {
                int l = i ^ j;
                if (l > i) {
                    unsigned a = skey[i], c = skey[l];
                    bool up = ((i & k) == 0);
                    if ((a > c) == up) { skey[i] = c; skey[l] = a; }
                }
            }
            __syncthreads();
        }
    }

    for (int i = threadIdx.x; i < NN; i += 256) {
        int si = (int)(skey[i] & 2047u);
        const float* p = src + (off + si) * 3;
        float x = p[0], y = p[1], z = p[2];
        dst[off + i] = make_float4(x, y, z, (x * x + y * y + z * z) * S2F);
        pot[off + i] = 0.f;
    }
}

// ---------------------------------------------------------------------------
#define MERGEROW(m, s, off)                                         \
    {                                                               \
        float mo = __shfl_xor_sync(0xffffffffu, m, off);            \
        float so = __shfl_xor_sync(0xffffffffu, s, off);            \
        float mn = fmaxf(m, mo);                                    \
        s = fmaf(so, ex2f_(mo - mn), s * ex2f_(m - mn));            \
        m = mn;                                                     \
    }

#define ROWUPD(m, s, mt, a, e)                                      \
    if (__any_sync(0xffffffffu, (e) > 0.f)) {                       \
        if (__any_sync(0xffffffffu, (a) > (m))) {                   \
            float c = fmaxf(m, a);                                  \
            c = fmaxf(c, __shfl_xor_sync(0xffffffffu, c, 16));      \
            c = fmaxf(c, __shfl_xor_sync(0xffffffffu, c, 8));       \
            c = fmaxf(c, __shfl_xor_sync(0xffffffffu, c, 4));       \
            c = fmaxf(c, __shfl_xor_sync(0xffffffffu, c, 2));       \
            c = fmaxf(c, __shfl_xor_sync(0xffffffffu, c, 1));       \
            s = fmaf(s, ex2f_(m - c), ex2f_((a) - c));              \
            m = c; mt = c - TT;                                     \
        } else {                                                    \
            s += ex2f_((a) - m);                                    \
        }                                                           \
    }

// Boot half-update (iteration 0): full online LSE, stores row max.
__global__ void __launch_bounds__(256) half_boot(int dir) {
    int blk = blockIdx.x;
    int b = blk >> 6;
    int chunk = blk & 63;

    const float4* R4  = dir ? d_Q4 : d_P4;
    const float4* D4  = dir ? d_P4 : d_Q4;
    const float*  pin = dir ? d_f  : d_g;
    float*        pout = dir ? d_g : d_f;
    float*        mout = dir ? d_mg : d_mf;

    __shared__ float4 tbl[NN];
    {
        const float4* Db = D4 + b * NN;
        const float*  pb = pin + b * NN;
        for (int j = threadIdx.x; j < NN; j += 256) {
            float4 q = Db[j];
            float4 t;
            t.x = q.x * S2X2;
            t.y = q.y * S2X2;
            t.z = q.z * S2X2;
            t.w = fmaf(pb[j], S2F, -q.w);
            tbl[j] = t;
        }
    }
    __syncthreads();

    int warp = threadIdx.x >> 5;
    int lane = threadIdx.x & 31;
    int row0 = b * NN + chunk * 32 + warp * 4;

    float4 r0 = R4[row0 + 0];
    float4 r1 = R4[row0 + 1];
    float4 r2 = R4[row0 + 2];
    float4 r3 = R4[row0 + 3];

    const float NEGINF = -CUDART_INF_F;
    float m0 = NEGINF, m1 = NEGINF, m2 = NEGINF, m3 = NEGINF;
    float s0 = 0.f, s1 = 0.f, s2 = 0.f, s3 = 0.f;
    float mt0 = NEGINF, mt1 = NEGINF, mt2 = NEGINF, mt3 = NEGINF;

#pragma unroll 2
    for (int k = 0; k < 64; ++k) {
        float4 q = tbl[(k << 5) + lane];
        float a0 = fmaf(r0.x, q.x, fmaf(r0.y, q.y, fmaf(r0.z, q.z, q.w)));
        float a1 = fmaf(r1.x, q.x, fmaf(r1.y, q.y, fmaf(r1.z, q.z, q.w)));
        float a2 = fmaf(r2.x, q.x, fmaf(r2.y, q.y, fmaf(r2.z, q.z, q.w)));
        float a3 = fmaf(r3.x, q.x, fmaf(r3.y, q.y, fmaf(r3.z, q.z, q.w)));
        float e0 = a0 - mt0;
        float e1 = a1 - mt1;
        float e2 = a2 - mt2;
        float e3 = a3 - mt3;
        float emax = fmaxf(fmaxf(e0, e1), fmaxf(e2, e3));
        if (__any_sync(0xffffffffu, emax > 0.f)) {
            ROWUPD(m0, s0, mt0, a0, e0)
            ROWUPD(m1, s1, mt1, a1, e1)
            ROWUPD(m2, s2, mt2, a2, e2)
            ROWUPD(m3, s3, mt3, a3, e3)
        }
    }

#pragma unroll
    for (int o = 16; o; o >>= 1) {
        MERGEROW(m0, s0, o);
        MERGEROW(m1, s1, o);
        MERGEROW(m2, s2, o);
        MERGEROW(m3, s3, o);
    }

    if (lane == 0) {
        pout[row0 + 0] = fmaf(-EPSLN2, (-r0.w) + m0 + lg2f_(s0), EPSLOGMU);
        pout[row0 + 1] = fmaf(-EPSLN2, (-r1.w) + m1 + lg2f_(s1), EPSLOGMU);
        pout[row0 + 2] = fmaf(-EPSLN2, (-r2.w) + m2 + lg2f_(s2), EPSLOGMU);
        pout[row0 + 3] = fmaf(-EPSLN2, (-r3.w) + m3 + lg2f_(s3), EPSLOGMU);
        mout[row0 + 0] = m0;
        mout[row0 + 1] = m1;
        mout[row0 + 2] = m2;
        mout[row0 + 3] = m3;
    }
}

// Fast half-update: BRANCH-FREE. s += ex2(a - muT) always; underflow = trunc.
__global__ void __launch_bounds__(256) half_fast(int dir) {
    int blk = blockIdx.x;
    int b = blk >> 6;
    int chunk = blk & 63;

    const float4* R4  = dir ? d_Q4 : d_P4;
    const float4* D4  = dir ? d_P4 : d_Q4;
    const float*  pin = dir ? d_f  : d_g;
    float*        pout = dir ? d_g : d_f;
    float*        marr = dir ? d_mg : d_mf;

    __shared__ float4 tbl[NN];
    {
        const float4* Db = D4 + b * NN;
        const float*  pb = pin + b * NN;
        for (int j = threadIdx.x; j < NN; j += 256) {
            float4 q = Db[j];
            float4 t;
            t.x = q.x * S2X2;
            t.y = q.y * S2X2;
            t.z = q.z * S2X2;
            t.w = fmaf(pb[j], S2F, -q.w);
            tbl[j] = t;
        }
    }
    __syncthreads();

    int warp = threadIdx.x >> 5;
    int lane = threadIdx.x & 31;
    int row0 = b * NN + chunk * 32 + warp * 4;

    float4 r0 = R4[row0 + 0];
    float4 r1 = R4[row0 + 1];
    float4 r2 = R4[row0 + 2];
    float4 r3 = R4[row0 + 3];

    float muT0 = marr[row0 + 0] - SLACKTT;
    float muT1 = marr[row0 + 1] - SLACKTT;
    float muT2 = marr[row0 + 2] - SLACKTT;
    float muT3 = marr[row0 + 3] - SLACKTT;

    const float NEGINF = -CUDART_INF_F;
    float s0 = 0.f, s1 = 0.f, s2 = 0.f, s3 = 0.f;
    float mx0 = NEGINF, mx1 = NEGINF, mx2 = NEGINF, mx3 = NEGINF;

#pragma unroll 4
    for (int k = 0; k < 64; ++k) {
        float4 q = tbl[(k << 5) + lane];
        float a0 = fmaf(r0.x, q.x, fmaf(r0.y, q.y, fmaf(r0.z, q.z, q.w)));
        float a1 = fmaf(r1.x, q.x, fmaf(r1.y, q.y, fmaf(r1.z, q.z, q.w)));
        float a2 = fmaf(r2.x, q.x, fmaf(r2.y, q.y, fmaf(r2.z, q.z, q.w)));
        float a3 = fmaf(r3.x, q.x, fmaf(r3.y, q.y, fmaf(r3.z, q.z, q.w)));
        mx0 = fmaxf(mx0, a0);
        mx1 = fmaxf(mx1, a1);
        mx2 = fmaxf(mx2, a2);
        mx3 = fmaxf(mx3, a3);
        s0 += ex2f_(a0 - muT0);
        s1 += ex2f_(a1 - muT1);
        s2 += ex2f_(a2 - muT2);
        s3 += ex2f_(a3 - muT3);
    }

#pragma unroll
    for (int o = 16; o; o >>= 1) {
        s0 += __shfl_xor_sync(0xffffffffu, s0, o);
        s1 += __shfl_xor_sync(0xffffffffu, s1, o);
        s2 += __shfl_xor_sync(0xffffffffu, s2, o);
        s3 += __shfl_xor_sync(0xffffffffu, s3, o);
        mx0 = fmaxf(mx0, __shfl_xor_sync(0xffffffffu, mx0, o));
        mx1 = fmaxf(mx1, __shfl_xor_sync(0xffffffffu, mx1, o));
        mx2 = fmaxf(mx2, __shfl_xor_sync(0xffffffffu, mx2, o));
        mx3 = fmaxf(mx3, __shfl_xor_sync(0xffffffffu, mx3, o));
    }

    if (lane == 0) {
        pout[row0 + 0] = fmaf(-EPSLN2, (-r0.w) + muT0 + lg2f_(s0), EPSLOGMU);
        pout[row0 + 1] = fmaf(-EPSLN2, (-r1.w) + muT1 + lg2f_(s1), EPSLOGMU);
        pout[row0 + 2] = fmaf(-EPSLN2, (-r2.w) + muT2 + lg2f_(s2), EPSLOGMU);
        pout[row0 + 3] = fmaf(-EPSLN2, (-r3.w) + muT3 + lg2f_(s3), EPSLOGMU);
        marr[row0 + 0] = mx0;
        marr[row0 + 1] = mx1;
        marr[row0 + 2] = mx2;
        marr[row0 + 3] = mx3;
    }
}

// ---------------------------------------------------------------------------
// Loss: BRANCH-FREE. part += ex2(arg) * C for every element.
__global__ void __launch_bounds__(256) loss_kernel() {
    int blk = blockIdx.x;
    int b = blk >> 6;
    int chunk = blk & 63;

    __shared__ float4 tbl[NN];
    __shared__ float  gg[NN];
    {
        const float4* Db = d_Q4 + b * NN;
        const float*  pb = d_g + b * NN;
        for (int j = threadIdx.x; j < NN; j += 256) {
            float4 q = Db[j];
            float gj = pb[j];
            float4 t;
            t.x = q.x * S2X2;
            t.y = q.y * S2X2;
            t.z = q.z * S2X2;
            t.w = fmaf(gj, S2F, -q.w);
            tbl[j] = t;
            gg[j] = gj;
        }
    }
    __syncthreads();

    int warp = threadIdx.x >> 5;
    int lane = threadIdx.x & 31;
    int row0 = b * NN + chunk * 32 + warp * 4;

    float4 r0 = d_P4[row0 + 0];
    float4 r1 = d_P4[row0 + 1];
    float4 r2 = d_P4[row0 + 2];
    float4 r3 = d_P4[row0 + 3];
    float fr0 = d_f[row0 + 0], fr1 = d_f[row0 + 1];
    float fr2 = d_f[row0 + 2], fr3 = d_f[row0 + 3];
    // ff = f*S2 - pp*S2: arg = a + ff = (f+g-C)/(eps*ln2) <= 0
    float ff0 = fmaf(fr0, S2F, -r0.w);
    float ff1 = fmaf(fr1, S2F, -r1.w);
    float ff2 = fmaf(fr2, S2F, -r2.w);
    float ff3 = fmaf(fr3, S2F, -r3.w);

    float part = 0.f;
#pragma unroll 2
    for (int k = 0; k < 64; ++k) {
        int j = (k << 5) + lane;
        float4 q = tbl[j];
        float gj = gg[j];
        {
            float a = fmaf(r0.x, q.x, fmaf(r0.y, q.y, fmaf(r0.z, q.z, q.w)));
            float arg = a + ff0;
            float C = fmaf(-EPSLN2, arg, fr0 + gj);
            part = fmaf(ex2f_(arg), C, part);
        }
        {
            float a = fmaf(r1.x, q.x, fmaf(r1.y, q.y, fmaf(r1.z, q.z, q.w)));
            float arg = a + ff1;
            float C = fmaf(-EPSLN2, arg, fr1 + gj);
            part = fmaf(ex2f_(arg), C, part);
        }
        {
            float a = fmaf(r2.x, q.x, fmaf(r2.y, q.y, fmaf(r2.z, q.z, q.w)));
            float arg = a + ff2;
            float C = fmaf(-EPSLN2, arg, fr2 + gj);
            part = fmaf(ex2f_(arg), C, part);
        }
        {
            float a = fmaf(r3.x, q.x, fmaf(r3.y, q.y, fmaf(r3.z, q.z, q.w)));
            float arg = a + ff3;
            float C = fmaf(-EPSLN2, arg, fr3 + gj);
            part = fmaf(ex2f_(arg), C, part);
        }
    }

    __shared__ float red[256];
    red[threadIdx.x] = part;
    __syncthreads();
#pragma unroll
    for (int o = 128; o; o >>= 1) {
        if (threadIdx.x < o) red[threadIdx.x] += red[threadIdx.x + o];
        __syncthreads();
    }
    if (threadIdx.x == 0) d_partials[blockIdx.x] = red[0];
}

__global__ void reduce_kernel(float* __restrict__ out) {
    __shared__ float red[256];
    float v = 0.f;
    for (int i = threadIdx.x; i < 512; i += 256) v += d_partials[i];
    red[threadIdx.x] = v;
    __syncthreads();
#pragma unroll
    for (int o = 128; o; o >>= 1) {
        if (threadIdx.x < o) red[threadIdx.x] += red[threadIdx.x + o];
        __syncthreads();
    }
    if (threadIdx.x == 0) out[0] = red[0] * 0.125f;
}

extern "C" void kernel_launch(void* const* d_in, const int* in_sizes, int n_in,
                              void* d_out, int out_size) {
    const float* preds = (const float*)d_in[0];
    const float* gts   = (const float*)d_in[1];
    float* out = (float*)d_out;

    prep_sort_kernel<<<BB * 2, 256>>>(preds, gts);
    half_boot<<<BB * 64, 256>>>(0);
    half_boot<<<BB * 64, 256>>>(1);
    for (int it = 1; it < 50; ++it) {
        half_fast<<<BB * 64, 256>>>(0);
        half_fast<<<BB * 64, 256>>>(1);
    }
    loss_kernel<<<BB * 64, 256>>>();
    reduce_kernel<<<1, 256>>>(out);
}